// round 1
// baseline (speedup 1.0000x reference)
#include <cuda_runtime.h>

// out = inputs * (noise >= 0.5f ? 2.0f : 0.0f)
// 67,108,864 fp32 elements, exactly divisible by 4 (float4) and by grid*block.

__global__ void __launch_bounds__(256)
sparse_dropout_vec4(const float4* __restrict__ inputs,
                    const float4* __restrict__ noise,
                    float4* __restrict__ out)
{
    const unsigned idx = blockIdx.x * blockDim.x + threadIdx.x;

    float4 x = inputs[idx];
    float4 n = noise[idx];

    float4 r;
    r.x = (n.x >= 0.5f) ? x.x * 2.0f : 0.0f;
    r.y = (n.y >= 0.5f) ? x.y * 2.0f : 0.0f;
    r.z = (n.z >= 0.5f) ? x.z * 2.0f : 0.0f;
    r.w = (n.w >= 0.5f) ? x.w * 2.0f : 0.0f;

    out[idx] = r;
}

extern "C" void kernel_launch(void* const* d_in, const int* in_sizes, int n_in,
                              void* d_out, int out_size)
{
    const float4* inputs = (const float4*)d_in[0];
    const float4* noise  = (const float4*)d_in[1];
    float4* out          = (float4*)d_out;

    // 16384*4096 = 67108864 elements = 16777216 float4
    const int n_vec4 = out_size / 4;
    const int threads = 256;
    const int blocks = (n_vec4 + threads - 1) / threads;  // 65536

    sparse_dropout_vec4<<<blocks, threads>>>(inputs, noise, out);
}